// round 16
// baseline (speedup 1.0000x reference)
#include <cuda_runtime.h>
#include <cuda_fp16.h>
#include <math.h>
#include <stdint.h>

#define BATCH 4
#define SEQ   2048
#define DIM   1024
#define NH    16
#define DKH   64
#define DFFN  4096
#define MROWS (BATCH*SEQ)
typedef long long ll;
typedef __half hf;

// ---------------- PTX helpers ----------------
__device__ __forceinline__ uint32_t smem_u32(const void* p) {
    uint32_t a;
    asm("{ .reg .u64 t; cvta.to.shared.u64 t, %1; cvt.u32.u64 %0, t; }" : "=r"(a) : "l"(p));
    return a;
}
__device__ __forceinline__ void cp16(uint32_t s, const void* g) {
    asm volatile("cp.async.cg.shared.global [%0], [%1], 16;" :: "r"(s), "l"(g));
}
#define CP_COMMIT() asm volatile("cp.async.commit_group;" ::: "memory")
#define CP_WAIT1()  asm volatile("cp.async.wait_group 1;" ::: "memory")
#define CP_WAIT0()  asm volatile("cp.async.wait_group 0;" ::: "memory")

#define LDSM4(r, a) asm volatile("ldmatrix.sync.aligned.m8n8.x4.shared.b16 {%0,%1,%2,%3}, [%4];" \
    : "=r"((r)[0]), "=r"((r)[1]), "=r"((r)[2]), "=r"((r)[3]) : "r"(a))
#define LDSM4T(r, a) asm volatile("ldmatrix.sync.aligned.m8n8.x4.trans.shared.b16 {%0,%1,%2,%3}, [%4];" \
    : "=r"((r)[0]), "=r"((r)[1]), "=r"((r)[2]), "=r"((r)[3]) : "r"(a))

// fp32-accum MMA (flash only)
#define MMA16816(c, a, b) asm volatile( \
    "mma.sync.aligned.m16n8k16.row.col.f32.f16.f16.f32 " \
    "{%0,%1,%2,%3}, {%4,%5,%6,%7}, {%8,%9}, {%0,%1,%2,%3};" \
    : "+f"((c)[0]), "+f"((c)[1]), "+f"((c)[2]), "+f"((c)[3]) \
    : "r"((a)[0]), "r"((a)[1]), "r"((a)[2]), "r"((a)[3]), "r"((b)[0]), "r"((b)[1]))

// fp16-accum MMA (2x rate; GEMM inner chunks)
#define MMA16816H(c, a, b) asm volatile( \
    "mma.sync.aligned.m16n8k16.row.col.f16.f16.f16.f16 " \
    "{%0,%1}, {%2,%3,%4,%5}, {%6,%7}, {%0,%1};" \
    : "+r"((c)[0]), "+r"((c)[1]) \
    : "r"((a)[0]), "r"((a)[1]), "r"((a)[2]), "r"((a)[3]), "r"((b)[0]), "r"((b)[1]))

// ---------------- scratch ----------------
__device__ hf    g_x16[(size_t)MROWS*DIM];
__device__ hf    g_qkv[(size_t)MROWS*3*DIM];
__device__ float g_gate[(size_t)MROWS*NH];
__device__ float g_wgT[(size_t)NH*DIM];
__device__ hf    g_ctx[(size_t)MROWS*DIM];
__device__ float g_y [(size_t)MROWS*DIM];
__device__ float g_x1[(size_t)MROWS*DIM];
__device__ hf    g_x116[(size_t)MROWS*DIM];
__device__ hf    g_h1[(size_t)MROWS*DFFN];
__device__ float g_y2[(size_t)MROWS*DIM];
__device__ hf    g_wqkvT[(size_t)3*DIM*DIM];
__device__ hf    g_woT[(size_t)DIM*DIM];
__device__ hf    g_w1T[(size_t)DIM*DFFN];
__device__ hf    g_w2T[(size_t)DIM*DFFN];
__device__ float g_bqkv[3*DIM];

__device__ __forceinline__ uint32_t pack2(float a, float b) {
    hf ah = __float2half_rn(a), bh = __float2half_rn(b);
    return ((uint32_t)*(uint16_t*)&bh << 16) | *(uint16_t*)&ah;
}

// ---------------- fp16-chunk-accum HMMA GEMM: BM=128, BN=128, 256 thr, 3-stage, 2 CTA/SM ----------------
// Per 64-K chunk: accumulate in fp16 (2x tensor rate), then promote into fp32.
// EPI bits: 1=bias, 2=resid, 4=gelu, 8=fp16 output (else fp32).
template<int EPI>
__global__ __launch_bounds__(256, 2)
void mma_gemm(const hf* __restrict__ A, int lda,
              const hf* __restrict__ B, int ldb,
              float* __restrict__ Cf, hf* __restrict__ Ch,
              int ldc, const float* __restrict__ bias, const float* __restrict__ resid,
              float alpha, int K)
{
    constexpr int BM = 128, BN = 128;
    constexpr int MT = 2, NT = 8;
    constexpr int ROWB = 144;
    constexpr int A_BYTES = BM * ROWB;
    constexpr int B_BYTES = BN * ROWB;
    constexpr int STAGE = A_BYTES + B_BYTES;
    constexpr int NSTAGE = 3;

    extern __shared__ __align__(128) char smem[];
    const uint32_t sb = smem_u32(smem);

    const int tid = threadIdx.x, wid = tid >> 5, lane = tid & 31;
    const int wm0 = (wid >> 1) * 32;
    const int wn0 = (wid & 1) * 64;

    const int m0 = blockIdx.y * BM, n0 = blockIdx.x * BN;
    const int C = K / 64;

    auto load_stage = [&](int c, int s) {
        const int kc = c * 64;
        const uint32_t base = sb + s * STAGE;
        #pragma unroll
        for (int i = tid; i < BM * 8; i += 256) {
            int row = i >> 3, c16 = i & 7;
            cp16(base + row * ROWB + c16 * 16,
                 A + (size_t)(m0 + row) * lda + kc + c16 * 8);
        }
        #pragma unroll
        for (int i = tid; i < BN * 8; i += 256) {
            int row = i >> 3, c16 = i & 7;
            cp16(base + A_BYTES + row * ROWB + c16 * 16,
                 B + (size_t)(n0 + row) * ldb + kc + c16 * 8);
        }
    };

    float acc[MT][NT][4];
    uint32_t a16[MT][NT][2];
    #pragma unroll
    for (int i = 0; i < MT; i++)
        #pragma unroll
        for (int j = 0; j < NT; j++) {
            #pragma unroll
            for (int t = 0; t < 4; t++) acc[i][j][t] = 0.f;
            a16[i][j][0] = 0u; a16[i][j][1] = 0u;
        }

    load_stage(0, 0);
    CP_COMMIT();
    if (C > 1) load_stage(1, 1);
    CP_COMMIT();

    for (int c = 0; c < C; c++) {
        CP_WAIT1();
        __syncthreads();
        if (c + 2 < C) { load_stage(c + 2, (c + 2) % NSTAGE); CP_COMMIT(); }

        const uint32_t base = sb + (c % NSTAGE) * STAGE;
        #pragma unroll
        for (int k16 = 0; k16 < 4; k16++) {
            uint32_t ah[MT][4];
            #pragma unroll
            for (int mt = 0; mt < MT; mt++) {
                uint32_t a = base + (wm0 + mt * 16 + (lane & 15)) * ROWB
                           + k16 * 32 + (lane >> 4) * 16;
                LDSM4(ah[mt], a);
            }
            #pragma unroll
            for (int np = 0; np < NT / 2; np++) {
                uint32_t bh[4];
                uint32_t b = base + A_BYTES
                           + (wn0 + (np * 2 + (lane >> 4)) * 8 + (lane & 7)) * ROWB
                           + k16 * 32 + ((lane >> 3) & 1) * 16;
                LDSM4(bh, b);
                #pragma unroll
                for (int mt = 0; mt < MT; mt++) {
                    MMA16816H(a16[mt][2*np],   ah[mt], bh);
                    MMA16816H(a16[mt][2*np+1], ah[mt], bh + 2);
                }
            }
        }
        // promote fp16 chunk accumulators into fp32
        #pragma unroll
        for (int mt = 0; mt < MT; mt++)
            #pragma unroll
            for (int nt = 0; nt < NT; nt++) {
                float2 f0 = __half22float2(*(__half2*)&a16[mt][nt][0]);
                float2 f1 = __half22float2(*(__half2*)&a16[mt][nt][1]);
                acc[mt][nt][0] += f0.x; acc[mt][nt][1] += f0.y;
                acc[mt][nt][2] += f1.x; acc[mt][nt][3] += f1.y;
                a16[mt][nt][0] = 0u; a16[mt][nt][1] = 0u;
            }
    }

    #pragma unroll
    for (int mt = 0; mt < MT; mt++) {
        #pragma unroll
        for (int nt = 0; nt < NT; nt++) {
            const int cb = n0 + wn0 + nt * 8 + (lane & 3) * 2;
            #pragma unroll
            for (int half = 0; half < 2; half++) {
                const int m = m0 + wm0 + mt * 16 + (lane >> 2) + half * 8;
                float v0 = acc[mt][nt][half * 2 + 0] * alpha;
                float v1 = acc[mt][nt][half * 2 + 1] * alpha;
                if (EPI & 1) { v0 += bias[cb]; v1 += bias[cb + 1]; }
                if (EPI & 4) {
                    v0 = 0.5f * v0 * (1.0f + erff(v0 * 0.70710678118654752f));
                    v1 = 0.5f * v1 * (1.0f + erff(v1 * 0.70710678118654752f));
                }
                if (EPI & 2) {
                    const float2 rv = *(const float2*)&resid[(size_t)m * ldc + cb];
                    v0 += rv.x; v1 += rv.y;
                }
                if (EPI & 8) {
                    *(uint32_t*)&Ch[(size_t)m * ldc + cb] = pack2(v0, v1);
                } else {
                    float2 ov = {v0, v1};
                    *(float2*)&Cf[(size_t)m * ldc + cb] = ov;
                }
            }
        }
    }
}

// ---------------- fused flash attention (fp32 accum; unchanged from R15) ----------------
__global__ __launch_bounds__(256, 2)
void flash_kernel(const hf* __restrict__ qkv,
                  const float* __restrict__ gate, const int* __restrict__ mask,
                  hf* __restrict__ ctx)
{
    constexpr int ROWB = 144;
    constexpr int QBYTES = 128 * ROWB;
    constexpr int KSTG = 64 * ROWB;
    constexpr int VSTG = 64 * ROWB;
    constexpr int OFF_Q = 0;
    constexpr int OFF_K = QBYTES;
    constexpr int OFF_V = OFF_K + 2 * KSTG;
    constexpr int OFF_M = OFF_V + 2 * VSTG;
    extern __shared__ __align__(128) char smem[];
    const uint32_t sb = smem_u32(smem);

    const int tid = threadIdx.x, wid = tid >> 5, lane = tid & 31;
    const int z = blockIdx.y, b = z >> 4, h = z & 15;
    const int q0 = blockIdx.x * 128;
    const int wq0 = wid * 16;
    const size_t qks = 3 * DIM;

    for (int i = tid; i < 128 * 8; i += 256) {
        int row = i >> 3, c = i & 7;
        cp16(sb + OFF_Q + row * ROWB + c * 16,
             qkv + (size_t)(b * SEQ + q0 + row) * qks + h * DKH + c * 8);
    }
    auto load_kv = [&](int kt, int st) {
        for (int i = tid; i < 64 * 8; i += 256) {
            int row = i >> 3, c = i & 7;
            cp16(sb + OFF_K + st * KSTG + row * ROWB + c * 16,
                 qkv + (size_t)(b * SEQ + kt * 64 + row) * qks + DIM + h * DKH + c * 8);
        }
        for (int i = tid; i < 64 * 8; i += 256) {
            int row = i >> 3, c = i & 7;
            cp16(sb + OFF_V + st * VSTG + row * ROWB + c * 16,
                 qkv + (size_t)(b * SEQ + kt * 64 + row) * qks + 2 * DIM + h * DKH + c * 8);
        }
        if (tid < 16) cp16(sb + OFF_M + st * 256 + tid * 16, mask + (size_t)b * SEQ + kt * 64 + tid * 4);
    };
    load_kv(0, 0);
    CP_COMMIT();
    CP_WAIT0();
    __syncthreads();

    uint32_t qh_[4][4];
    #pragma unroll
    for (int kk = 0; kk < 4; kk++) {
        uint32_t a = sb + OFF_Q + (wq0 + (lane & 15)) * ROWB + kk * 32 + (lane >> 4) * 16;
        LDSM4(qh_[kk], a);
    }

    float o[8][4];
    #pragma unroll
    for (int nt = 0; nt < 8; nt++)
        #pragma unroll
        for (int t = 0; t < 4; t++) o[nt][t] = 0.f;
    float m0 = -3e38f, m1 = -3e38f, l0 = 0.f, l1 = 0.f;

    for (int kt = 0; kt < 32; kt++) {
        if (kt) { CP_WAIT0(); __syncthreads(); }
        if (kt + 1 < 32) { load_kv(kt + 1, (kt + 1) & 1); CP_COMMIT(); }
        const int st = kt & 1;

        float s[8][4];
        #pragma unroll
        for (int nt = 0; nt < 8; nt++)
            #pragma unroll
            for (int t = 0; t < 4; t++) s[nt][t] = 0.f;
        const uint32_t kb_ = sb + OFF_K + st * KSTG;
        #pragma unroll
        for (int kk = 0; kk < 4; kk++) {
            #pragma unroll
            for (int np = 0; np < 4; np++) {
                uint32_t kbh[4];
                uint32_t a = kb_ + ((np * 2 + (lane >> 4)) * 8 + (lane & 7)) * ROWB
                           + kk * 32 + ((lane >> 3) & 1) * 16;
                LDSM4(kbh, a);
                MMA16816(s[2*np],   qh_[kk], kbh);
                MMA16816(s[2*np+1], qh_[kk], kbh + 2);
            }
        }

        float nm0 = -3e38f, nm1 = -3e38f;
        const char* mb_ = smem + OFF_M + st * 256;
        #pragma unroll
        for (int nt = 0; nt < 8; nt++) {
            int2 mm = *(const int2*)(mb_ + (nt * 8 + (lane & 3) * 2) * 4);
            s[nt][0] = mm.x ? s[nt][0] * 0.125f : -1e9f;
            s[nt][1] = mm.y ? s[nt][1] * 0.125f : -1e9f;
            s[nt][2] = mm.x ? s[nt][2] * 0.125f : -1e9f;
            s[nt][3] = mm.y ? s[nt][3] * 0.125f : -1e9f;
            nm0 = fmaxf(nm0, fmaxf(s[nt][0], s[nt][1]));
            nm1 = fmaxf(nm1, fmaxf(s[nt][2], s[nt][3]));
        }
        nm0 = fmaxf(nm0, __shfl_xor_sync(0xffffffffu, nm0, 1));
        nm0 = fmaxf(nm0, __shfl_xor_sync(0xffffffffu, nm0, 2));
        nm1 = fmaxf(nm1, __shfl_xor_sync(0xffffffffu, nm1, 1));
        nm1 = fmaxf(nm1, __shfl_xor_sync(0xffffffffu, nm1, 2));
        float mn0 = fmaxf(m0, nm0), mn1 = fmaxf(m1, nm1);
        float sc0 = __expf(m0 - mn0), sc1 = __expf(m1 - mn1);
        m0 = mn0; m1 = mn1;
        float ls0 = 0.f, ls1 = 0.f;
        #pragma unroll
        for (int nt = 0; nt < 8; nt++) {
            s[nt][0] = __expf(s[nt][0] - m0);
            s[nt][1] = __expf(s[nt][1] - m0);
            s[nt][2] = __expf(s[nt][2] - m1);
            s[nt][3] = __expf(s[nt][3] - m1);
            ls0 += s[nt][0] + s[nt][1];
            ls1 += s[nt][2] + s[nt][3];
        }
        ls0 += __shfl_xor_sync(0xffffffffu, ls0, 1);
        ls0 += __shfl_xor_sync(0xffffffffu, ls0, 2);
        ls1 += __shfl_xor_sync(0xffffffffu, ls1, 1);
        ls1 += __shfl_xor_sync(0xffffffffu, ls1, 2);
        l0 = l0 * sc0 + ls0;
        l1 = l1 * sc1 + ls1;
        #pragma unroll
        for (int nt = 0; nt < 8; nt++) {
            o[nt][0] *= sc0; o[nt][1] *= sc0;
            o[nt][2] *= sc1; o[nt][3] *= sc1;
        }

        const uint32_t vb_ = sb + OFF_V + st * VSTG;
        #pragma unroll
        for (int j = 0; j < 4; j++) {
            uint32_t p[4];
            p[0] = pack2(s[2*j][0],   s[2*j][1]);
            p[1] = pack2(s[2*j][2],   s[2*j][3]);
            p[2] = pack2(s[2*j+1][0], s[2*j+1][1]);
            p[3] = pack2(s[2*j+1][2], s[2*j+1][3]);
            #pragma unroll
            for (int np = 0; np < 4; np++) {
                uint32_t vbh[4];
                uint32_t a = vb_ + (j * 16 + (lane & 15)) * ROWB
                           + (np * 16 + (lane >> 4) * 8) * 2;
                LDSM4T(vbh, a);
                MMA16816(o[2*np],   p, vbh);
                MMA16816(o[2*np+1], p, vbh + 2);
            }
        }
    }

    const int sp0 = q0 + wq0 + (lane >> 2);
    float g0 = gate[((size_t)b * SEQ + sp0) * NH + h] / l0;
    float g1 = gate[((size_t)b * SEQ + sp0 + 8) * NH + h] / l1;
    const size_t r0 = ((size_t)b * SEQ + sp0) * DIM + h * DKH;
    const size_t r1 = r0 + (size_t)8 * DIM;
    #pragma unroll
    for (int nt = 0; nt < 8; nt++) {
        const int col = nt * 8 + (lane & 3) * 2;
        *(uint32_t*)&ctx[r0 + col] = pack2(o[nt][0] * g0, o[nt][1] * g0);
        *(uint32_t*)&ctx[r1 + col] = pack2(o[nt][2] * g1, o[nt][3] * g1);
    }
}

// ---------------- mega prep kernel ----------------
__device__ void tsplit_body(const float* __restrict__ W, hf* __restrict__ T,
                            int K, int N, int bx, int by)
{
    __shared__ float t[32][33];
    int tx = threadIdx.x & 31, ty = threadIdx.x >> 5;
    int n0 = bx * 32, k0 = by * 32;
    #pragma unroll
    for (int i = 0; i < 4; i++)
        t[ty + i * 8][tx] = W[(size_t)(k0 + ty + i * 8) * N + n0 + tx];
    __syncthreads();
    #pragma unroll
    for (int i = 0; i < 4; i++)
        T[(size_t)(n0 + ty + i * 8) * K + k0 + tx] = __float2half_rn(t[tx][ty + i * 8]);
}

__global__ __launch_bounds__(256)
void prep_kernel(const float* __restrict__ x,
                 const float* __restrict__ wq, const float* __restrict__ wk,
                 const float* __restrict__ wv, const float* __restrict__ wo,
                 const float* __restrict__ w1, const float* __restrict__ w2,
                 const float* __restrict__ bq, const float* __restrict__ bk,
                 const float* __restrict__ bv, const float* __restrict__ wg,
                 hf* __restrict__ x16,
                 hf* __restrict__ wqkvT, hf* __restrict__ woT,
                 hf* __restrict__ w1T, hf* __restrict__ w2T,
                 float* __restrict__ bqkv, float* __restrict__ wgT)
{
    int id = blockIdx.x;
    if (id < 8192) {
        int i = id * 256 + threadIdx.x;
        float4 v = ((const float4*)x)[i];
        uint32_t pk[2] = {pack2(v.x, v.y), pack2(v.z, v.w)};
        ((uint2*)x16)[i] = *(uint2*)pk;
        return;
    }
    id -= 8192;
    if (id < 4096) {
        int w = id >> 10, r = id & 1023;
        const float* W = (w == 0) ? wq : (w == 1) ? wk : (w == 2) ? wv : wo;
        hf* T = (w < 3) ? wqkvT + (size_t)w * DIM * DIM : woT;
        tsplit_body(W, T, DIM, DIM, r & 31, r >> 5);
        return;
    }
    id -= 4096;
    if (id < 4096) {
        tsplit_body(w1, w1T, DIM, DFFN, id & 127, id >> 7);
        return;
    }
    id -= 4096;
    if (id < 4096) {
        tsplit_body(w2, w2T, DFFN, DIM, id & 31, id >> 5);
        return;
    }
    id -= 4096;
    if (id == 0) {
        for (int i = threadIdx.x; i < DIM; i += 256) {
            bqkv[i] = bq[i]; bqkv[DIM + i] = bk[i]; bqkv[2 * DIM + i] = bv[i];
        }
        for (int i = threadIdx.x; i < DIM * NH; i += 256)
            wgT[(i % NH) * DIM + i / NH] = wg[i];
    }
}

// ---------------- gate (coalesced wgT) ----------------
__global__ __launch_bounds__(256)
void gate_kernel(const float* __restrict__ x, const float* __restrict__ wgT,
                 const float* __restrict__ bg, float* __restrict__ gate)
{
    __shared__ float xs[8][DIM];
    int row0 = blockIdx.x * 8;
    for (int i = threadIdx.x; i < 8 * DIM; i += 256)
        ((float*)xs)[i] = x[(size_t)row0 * DIM + i];
    __syncthreads();
    int w = threadIdx.x >> 5, lane = threadIdx.x & 31;
    for (int t = w; t < 8 * NH; t += 8) {
        int r = t >> 4, h = t & 15;
        float s = 0.f;
        for (int d = lane; d < DIM; d += 32) s += xs[r][d] * wgT[h * DIM + d];
        #pragma unroll
        for (int o = 16; o; o >>= 1) s += __shfl_xor_sync(0xffffffffu, s, o);
        if (lane == 0)
            gate[(size_t)(row0 + r) * NH + h] = 1.f / (1.f + __expf(-(s + bg[h])));
    }
}

// ---------------- layernorm ----------------
__device__ __forceinline__ float blk_red(float v, float* sm, bool mx) {
    int lane = threadIdx.x & 31, w = threadIdx.x >> 5;
    #pragma unroll
    for (int o = 16; o; o >>= 1) {
        float t = __shfl_xor_sync(0xffffffffu, v, o);
        v = mx ? fmaxf(v, t) : v + t;
    }
    if (lane == 0) sm[w] = v;
    __syncthreads();
    if (w == 0) {
        float t = (lane < 8) ? sm[lane] : (mx ? -3.4e38f : 0.f);
        #pragma unroll
        for (int o = 4; o; o >>= 1) {
            float u = __shfl_xor_sync(0xffffffffu, t, o);
            t = mx ? fmaxf(t, u) : t + u;
        }
        if (lane == 0) sm[0] = t;
    }
    __syncthreads();
    float r = sm[0];
    __syncthreads();
    return r;
}

__global__ __launch_bounds__(256)
void ln_kernel(const float* __restrict__ in, const float* __restrict__ gamma,
               const float* __restrict__ beta, float* __restrict__ out,
               hf* __restrict__ o16)
{
    __shared__ float sm[32];
    int row = blockIdx.x;
    const float4 v = ((const float4*)(in + (size_t)row * DIM))[threadIdx.x];
    float s  = v.x + v.y + v.z + v.w;
    float s2 = v.x*v.x + v.y*v.y + v.z*v.z + v.w*v.w;
    s  = blk_red(s,  sm, false);
    s2 = blk_red(s2, sm, false);
    float mu  = s * (1.f / DIM);
    float var = s2 * (1.f / DIM) - mu * mu;
    float rs  = rsqrtf(var + 1e-5f);
    int n = threadIdx.x * 4;
    float4 gv = *(const float4*)(gamma + n);
    float4 bv = *(const float4*)(beta + n);
    float o[4] = {(v.x-mu)*rs*gv.x+bv.x, (v.y-mu)*rs*gv.y+bv.y,
                  (v.z-mu)*rs*gv.z+bv.z, (v.w-mu)*rs*gv.w+bv.w};
    ((float4*)(out + (size_t)row * DIM))[threadIdx.x] = make_float4(o[0],o[1],o[2],o[3]);
    if (o16) {
        uint32_t pk[2] = {pack2(o[0], o[1]), pack2(o[2], o[3])};
        *(uint2*)(o16 + (size_t)row * DIM + n) = *(uint2*)pk;
    }
}

// ---------------- launch ----------------
static const int SMGM = 3 * (128 * 144 + 128 * 144);   // 110592 (2 CTAs/SM)
static const int SMFL = 128 * 144 + 2 * (64 * 144) + 2 * (64 * 144) + 512; // 55808

extern "C" void kernel_launch(void* const* d_in, const int* in_sizes, int n_in,
                              void* d_out, int out_size)
{
    const float* x   = (const float*)d_in[0];
    const float* w_q = (const float*)d_in[1];  const float* b_q = (const float*)d_in[2];
    const float* w_k = (const float*)d_in[3];  const float* b_k = (const float*)d_in[4];
    const float* w_v = (const float*)d_in[5];  const float* b_v = (const float*)d_in[6];
    const float* w_o = (const float*)d_in[7];  const float* b_o = (const float*)d_in[8];
    const float* w_g = (const float*)d_in[9];  const float* b_g = (const float*)d_in[10];
    const float* w1  = (const float*)d_in[11]; const float* b1  = (const float*)d_in[12];
    const float* w2  = (const float*)d_in[13]; const float* b2  = (const float*)d_in[14];
    const float* g1  = (const float*)d_in[15]; const float* be1 = (const float*)d_in[16];
    const float* g2  = (const float*)d_in[17]; const float* be2 = (const float*)d_in[18];
    const int*  mask = (const int*)  d_in[19];
    float* out = (float*)d_out;

    #define SYM(p, s) void* p; cudaGetSymbolAddress(&p, s)
    SYM(x16, g_x16); SYM(qkv, g_qkv);
    SYM(gate, g_gate); SYM(wgT, g_wgT); SYM(ctx, g_ctx);
    SYM(y, g_y); SYM(x1, g_x1); SYM(x116, g_x116);
    SYM(h1, g_h1); SYM(y2, g_y2);
    SYM(wqkvT, g_wqkvT); SYM(woT, g_woT);
    SYM(w1T, g_w1T); SYM(w2T, g_w2T);
    SYM(bqkv, g_bqkv);
    #undef SYM

    cudaFuncSetAttribute(mma_gemm<9>,  cudaFuncAttributeMaxDynamicSharedMemorySize, SMGM);
    cudaFuncSetAttribute(mma_gemm<3>,  cudaFuncAttributeMaxDynamicSharedMemorySize, SMGM);
    cudaFuncSetAttribute(mma_gemm<13>, cudaFuncAttributeMaxDynamicSharedMemorySize, SMGM);
    cudaFuncSetAttribute(flash_kernel, cudaFuncAttributeMaxDynamicSharedMemorySize, SMFL);

    dim3 tb(256);
    // 1: prep
    prep_kernel<<<20481, tb>>>(x, w_q, w_k, w_v, w_o, w1, w2, b_q, b_k, b_v, w_g,
        (hf*)x16, (hf*)wqkvT, (hf*)woT, (hf*)w1T, (hf*)w2T,
        (float*)bqkv, (float*)wgT);

    // 2: merged QKV  [8192, 3072]
    mma_gemm<9><<<dim3(24, 64, 1), tb, SMGM>>>(
        (hf*)x16, DIM, (hf*)wqkvT, DIM,
        nullptr, (hf*)qkv, 3*DIM, (float*)bqkv, nullptr, 1.f, DIM);

    // 3: gate
    gate_kernel<<<MROWS / 8, tb>>>(x, (float*)wgT, b_g, (float*)gate);

    // 4: fused attention
    flash_kernel<<<dim3(SEQ/128, BATCH*NH), tb, SMFL>>>(
        (hf*)qkv, (float*)gate, mask, (hf*)ctx);

    // 5: y = x + ctx @ w_o + b_o
    mma_gemm<3><<<dim3(8, 64, 1), tb, SMGM>>>(
        (hf*)ctx, DIM, (hf*)woT, DIM,
        (float*)y, nullptr, DIM, b_o, x, 1.f, DIM);

    // 6: x1 = LN(y)
    ln_kernel<<<MROWS, tb>>>((float*)y, g1, be1, (float*)x1, (hf*)x116);

    // 7: h1 = gelu(x1 @ w1 + b1)
    mma_gemm<13><<<dim3(32, 64, 1), tb, SMGM>>>(
        (hf*)x116, DIM, (hf*)w1T, DIM,
        nullptr, (hf*)h1, DFFN, b1, nullptr, 1.f, DIM);

    // 8: y2 = x1 + h1 @ w2 + b2
    mma_gemm<3><<<dim3(8, 64, 1), tb, SMGM>>>(
        (hf*)h1, DFFN, (hf*)w2T, DFFN,
        (float*)y2, nullptr, DIM, b2, (const float*)x1, 1.f, DFFN);

    // 9: out = LN(y2)
    ln_kernel<<<MROWS, tb>>>((float*)y2, g2, be2, out, nullptr);
}

// round 17
// speedup vs baseline: 1.1715x; 1.1715x over previous
#include <cuda_runtime.h>
#include <cuda_fp16.h>
#include <math.h>
#include <stdint.h>

#define BATCH 4
#define SEQ   2048
#define DIM   1024
#define NH    16
#define DKH   64
#define DFFN  4096
#define MROWS (BATCH*SEQ)
typedef long long ll;
typedef __half hf;

// ---------------- PTX helpers ----------------
__device__ __forceinline__ uint32_t smem_u32(const void* p) {
    uint32_t a;
    asm("{ .reg .u64 t; cvta.to.shared.u64 t, %1; cvt.u32.u64 %0, t; }" : "=r"(a) : "l"(p));
    return a;
}
__device__ __forceinline__ void cp16(uint32_t s, const void* g) {
    asm volatile("cp.async.cg.shared.global [%0], [%1], 16;" :: "r"(s), "l"(g));
}
#define CP_COMMIT() asm volatile("cp.async.commit_group;" ::: "memory")
#define CP_WAIT1()  asm volatile("cp.async.wait_group 1;" ::: "memory")
#define CP_WAIT0()  asm volatile("cp.async.wait_group 0;" ::: "memory")

#define LDSM4(r, a) asm volatile("ldmatrix.sync.aligned.m8n8.x4.shared.b16 {%0,%1,%2,%3}, [%4];" \
    : "=r"((r)[0]), "=r"((r)[1]), "=r"((r)[2]), "=r"((r)[3]) : "r"(a))
#define LDSM4T(r, a) asm volatile("ldmatrix.sync.aligned.m8n8.x4.trans.shared.b16 {%0,%1,%2,%3}, [%4];" \
    : "=r"((r)[0]), "=r"((r)[1]), "=r"((r)[2]), "=r"((r)[3]) : "r"(a))

#define MMA16816(c, a, b) asm volatile( \
    "mma.sync.aligned.m16n8k16.row.col.f32.f16.f16.f32 " \
    "{%0,%1,%2,%3}, {%4,%5,%6,%7}, {%8,%9}, {%0,%1,%2,%3};" \
    : "+f"((c)[0]), "+f"((c)[1]), "+f"((c)[2]), "+f"((c)[3]) \
    : "r"((a)[0]), "r"((a)[1]), "r"((a)[2]), "r"((a)[3]), "r"((b)[0]), "r"((b)[1]))

// ---------------- scratch ----------------
__device__ hf    g_x16[(size_t)MROWS*DIM];
__device__ hf    g_qkv[(size_t)MROWS*3*DIM];
__device__ float g_gate[(size_t)MROWS*NH];
__device__ float g_wgT[(size_t)NH*DIM];
__device__ hf    g_ctx[(size_t)MROWS*DIM];
__device__ float g_y [(size_t)MROWS*DIM];
__device__ float g_x1[(size_t)MROWS*DIM];
__device__ hf    g_x116[(size_t)MROWS*DIM];
__device__ hf    g_h1[(size_t)MROWS*DFFN];
__device__ float g_y2[(size_t)MROWS*DIM];
__device__ hf    g_wqkvT[(size_t)3*DIM*DIM];
__device__ hf    g_woT[(size_t)DIM*DIM];
__device__ hf    g_w1T[(size_t)DIM*DFFN];
__device__ hf    g_w2T[(size_t)DIM*DFFN];
__device__ float g_bqkv[3*DIM];

__device__ __forceinline__ uint32_t pack2(float a, float b) {
    hf ah = __float2half_rn(a), bh = __float2half_rn(b);
    return ((uint32_t)*(uint16_t*)&bh << 16) | *(uint16_t*)&ah;
}

// ---------------- single-fp16 HMMA GEMM: BM=128, BN=128, 256 threads, 3-stage, 2 CTAs/SM ----------------
// 8 warps: warp grid 4x2, warp tile 32x64 (MT=2, NT=8).
// EPI bits: 1=bias, 2=resid, 4=gelu, 8=fp16 output (else fp32).
template<int EPI>
__global__ __launch_bounds__(256, 2)
void mma_gemm(const hf* __restrict__ A, int lda,
              const hf* __restrict__ B, int ldb,
              float* __restrict__ Cf, hf* __restrict__ Ch,
              int ldc, const float* __restrict__ bias, const float* __restrict__ resid,
              float alpha, int K)
{
    constexpr int BM = 128, BN = 128;
    constexpr int MT = 2, NT = 8;
    constexpr int ROWB = 144;
    constexpr int A_BYTES = BM * ROWB;      // 18432
    constexpr int B_BYTES = BN * ROWB;      // 18432
    constexpr int STAGE = A_BYTES + B_BYTES;// 36864
    constexpr int NSTAGE = 3;               // 110592 total

    extern __shared__ __align__(128) char smem[];
    const uint32_t sb = smem_u32(smem);

    const int tid = threadIdx.x, wid = tid >> 5, lane = tid & 31;
    const int wm0 = (wid >> 1) * 32;
    const int wn0 = (wid & 1) * 64;

    const int m0 = blockIdx.y * BM, n0 = blockIdx.x * BN;
    const int C = K / 64;

    auto load_stage = [&](int c, int s) {
        const int kc = c * 64;
        const uint32_t base = sb + s * STAGE;
        #pragma unroll
        for (int i = tid; i < BM * 8; i += 256) {
            int row = i >> 3, c16 = i & 7;
            cp16(base + row * ROWB + c16 * 16,
                 A + (size_t)(m0 + row) * lda + kc + c16 * 8);
        }
        #pragma unroll
        for (int i = tid; i < BN * 8; i += 256) {
            int row = i >> 3, c16 = i & 7;
            cp16(base + A_BYTES + row * ROWB + c16 * 16,
                 B + (size_t)(n0 + row) * ldb + kc + c16 * 8);
        }
    };

    float acc[MT][NT][4];
    #pragma unroll
    for (int i = 0; i < MT; i++)
        #pragma unroll
        for (int j = 0; j < NT; j++)
            #pragma unroll
            for (int t = 0; t < 4; t++) acc[i][j][t] = 0.f;

    load_stage(0, 0);
    CP_COMMIT();
    if (C > 1) load_stage(1, 1);
    CP_COMMIT();

    for (int c = 0; c < C; c++) {
        CP_WAIT1();
        __syncthreads();
        if (c + 2 < C) { load_stage(c + 2, (c + 2) % NSTAGE); CP_COMMIT(); }

        const uint32_t base = sb + (c % NSTAGE) * STAGE;
        #pragma unroll
        for (int k16 = 0; k16 < 4; k16++) {
            uint32_t ah[MT][4];
            #pragma unroll
            for (int mt = 0; mt < MT; mt++) {
                uint32_t a = base + (wm0 + mt * 16 + (lane & 15)) * ROWB
                           + k16 * 32 + (lane >> 4) * 16;
                LDSM4(ah[mt], a);
            }
            #pragma unroll
            for (int np = 0; np < NT / 2; np++) {
                uint32_t bh[4];
                uint32_t b = base + A_BYTES
                           + (wn0 + (np * 2 + (lane >> 4)) * 8 + (lane & 7)) * ROWB
                           + k16 * 32 + ((lane >> 3) & 1) * 16;
                LDSM4(bh, b);
                #pragma unroll
                for (int mt = 0; mt < MT; mt++) {
                    MMA16816(acc[mt][2*np],   ah[mt], bh);
                    MMA16816(acc[mt][2*np+1], ah[mt], bh + 2);
                }
            }
        }
    }

    #pragma unroll
    for (int mt = 0; mt < MT; mt++) {
        #pragma unroll
        for (int nt = 0; nt < NT; nt++) {
            const int cb = n0 + wn0 + nt * 8 + (lane & 3) * 2;
            #pragma unroll
            for (int half = 0; half < 2; half++) {
                const int m = m0 + wm0 + mt * 16 + (lane >> 2) + half * 8;
                float v0 = acc[mt][nt][half * 2 + 0] * alpha;
                float v1 = acc[mt][nt][half * 2 + 1] * alpha;
                if (EPI & 1) { v0 += bias[cb]; v1 += bias[cb + 1]; }
                if (EPI & 4) {
                    v0 = 0.5f * v0 * (1.0f + erff(v0 * 0.70710678118654752f));
                    v1 = 0.5f * v1 * (1.0f + erff(v1 * 0.70710678118654752f));
                }
                if (EPI & 2) {
                    const float2 rv = *(const float2*)&resid[(size_t)m * ldc + cb];
                    v0 += rv.x; v1 += rv.y;
                }
                if (EPI & 8) {
                    *(uint32_t*)&Ch[(size_t)m * ldc + cb] = pack2(v0, v1);
                } else {
                    float2 ov = {v0, v1};
                    *(float2*)&Cf[(size_t)m * ldc + cb] = ov;
                }
            }
        }
    }
}

// ---------------- fused flash attention (fp32 accum, trans-V) ----------------
__global__ __launch_bounds__(256, 2)
void flash_kernel(const hf* __restrict__ qkv,
                  const float* __restrict__ gate, const int* __restrict__ mask,
                  hf* __restrict__ ctx)
{
    constexpr int ROWB = 144;
    constexpr int QBYTES = 128 * ROWB;
    constexpr int KSTG = 64 * ROWB;
    constexpr int VSTG = 64 * ROWB;
    constexpr int OFF_Q = 0;
    constexpr int OFF_K = QBYTES;
    constexpr int OFF_V = OFF_K + 2 * KSTG;
    constexpr int OFF_M = OFF_V + 2 * VSTG;
    extern __shared__ __align__(128) char smem[];
    const uint32_t sb = smem_u32(smem);

    const int tid = threadIdx.x, wid = tid >> 5, lane = tid & 31;
    const int z = blockIdx.y, b = z >> 4, h = z & 15;
    const int q0 = blockIdx.x * 128;
    const int wq0 = wid * 16;
    const size_t qks = 3 * DIM;

    for (int i = tid; i < 128 * 8; i += 256) {
        int row = i >> 3, c = i & 7;
        cp16(sb + OFF_Q + row * ROWB + c * 16,
             qkv + (size_t)(b * SEQ + q0 + row) * qks + h * DKH + c * 8);
    }
    auto load_kv = [&](int kt, int st) {
        for (int i = tid; i < 64 * 8; i += 256) {
            int row = i >> 3, c = i & 7;
            cp16(sb + OFF_K + st * KSTG + row * ROWB + c * 16,
                 qkv + (size_t)(b * SEQ + kt * 64 + row) * qks + DIM + h * DKH + c * 8);
        }
        for (int i = tid; i < 64 * 8; i += 256) {
            int row = i >> 3, c = i & 7;
            cp16(sb + OFF_V + st * VSTG + row * ROWB + c * 16,
                 qkv + (size_t)(b * SEQ + kt * 64 + row) * qks + 2 * DIM + h * DKH + c * 8);
        }
        if (tid < 16) cp16(sb + OFF_M + st * 256 + tid * 16, mask + (size_t)b * SEQ + kt * 64 + tid * 4);
    };
    load_kv(0, 0);
    CP_COMMIT();
    CP_WAIT0();
    __syncthreads();

    uint32_t qh_[4][4];
    #pragma unroll
    for (int kk = 0; kk < 4; kk++) {
        uint32_t a = sb + OFF_Q + (wq0 + (lane & 15)) * ROWB + kk * 32 + (lane >> 4) * 16;
        LDSM4(qh_[kk], a);
    }

    float o[8][4];
    #pragma unroll
    for (int nt = 0; nt < 8; nt++)
        #pragma unroll
        for (int t = 0; t < 4; t++) o[nt][t] = 0.f;
    float m0 = -3e38f, m1 = -3e38f, l0 = 0.f, l1 = 0.f;

    for (int kt = 0; kt < 32; kt++) {
        if (kt) { CP_WAIT0(); __syncthreads(); }
        if (kt + 1 < 32) { load_kv(kt + 1, (kt + 1) & 1); CP_COMMIT(); }
        const int st = kt & 1;

        float s[8][4];
        #pragma unroll
        for (int nt = 0; nt < 8; nt++)
            #pragma unroll
            for (int t = 0; t < 4; t++) s[nt][t] = 0.f;
        const uint32_t kb_ = sb + OFF_K + st * KSTG;
        #pragma unroll
        for (int kk = 0; kk < 4; kk++) {
            #pragma unroll
            for (int np = 0; np < 4; np++) {
                uint32_t kbh[4];
                uint32_t a = kb_ + ((np * 2 + (lane >> 4)) * 8 + (lane & 7)) * ROWB
                           + kk * 32 + ((lane >> 3) & 1) * 16;
                LDSM4(kbh, a);
                MMA16816(s[2*np],   qh_[kk], kbh);
                MMA16816(s[2*np+1], qh_[kk], kbh + 2);
            }
        }

        float nm0 = -3e38f, nm1 = -3e38f;
        const char* mb_ = smem + OFF_M + st * 256;
        #pragma unroll
        for (int nt = 0; nt < 8; nt++) {
            int2 mm = *(const int2*)(mb_ + (nt * 8 + (lane & 3) * 2) * 4);
            s[nt][0] = mm.x ? s[nt][0] * 0.125f : -1e9f;
            s[nt][1] = mm.y ? s[nt][1] * 0.125f : -1e9f;
            s[nt][2] = mm.x ? s[nt][2] * 0.125f : -1e9f;
            s[nt][3] = mm.y ? s[nt][3] * 0.125f : -1e9f;
            nm0 = fmaxf(nm0, fmaxf(s[nt][0], s[nt][1]));
            nm1 = fmaxf(nm1, fmaxf(s[nt][2], s[nt][3]));
        }
        nm0 = fmaxf(nm0, __shfl_xor_sync(0xffffffffu, nm0, 1));
        nm0 = fmaxf(nm0, __shfl_xor_sync(0xffffffffu, nm0, 2));
        nm1 = fmaxf(nm1, __shfl_xor_sync(0xffffffffu, nm1, 1));
        nm1 = fmaxf(nm1, __shfl_xor_sync(0xffffffffu, nm1, 2));
        float mn0 = fmaxf(m0, nm0), mn1 = fmaxf(m1, nm1);
        float sc0 = __expf(m0 - mn0), sc1 = __expf(m1 - mn1);
        m0 = mn0; m1 = mn1;
        float ls0 = 0.f, ls1 = 0.f;
        #pragma unroll
        for (int nt = 0; nt < 8; nt++) {
            s[nt][0] = __expf(s[nt][0] - m0);
            s[nt][1] = __expf(s[nt][1] - m0);
            s[nt][2] = __expf(s[nt][2] - m1);
            s[nt][3] = __expf(s[nt][3] - m1);
            ls0 += s[nt][0] + s[nt][1];
            ls1 += s[nt][2] + s[nt][3];
        }
        ls0 += __shfl_xor_sync(0xffffffffu, ls0, 1);
        ls0 += __shfl_xor_sync(0xffffffffu, ls0, 2);
        ls1 += __shfl_xor_sync(0xffffffffu, ls1, 1);
        ls1 += __shfl_xor_sync(0xffffffffu, ls1, 2);
        l0 = l0 * sc0 + ls0;
        l1 = l1 * sc1 + ls1;
        #pragma unroll
        for (int nt = 0; nt < 8; nt++) {
            o[nt][0] *= sc0; o[nt][1] *= sc0;
            o[nt][2] *= sc1; o[nt][3] *= sc1;
        }

        const uint32_t vb_ = sb + OFF_V + st * VSTG;
        #pragma unroll
        for (int j = 0; j < 4; j++) {
            uint32_t p[4];
            p[0] = pack2(s[2*j][0],   s[2*j][1]);
            p[1] = pack2(s[2*j][2],   s[2*j][3]);
            p[2] = pack2(s[2*j+1][0], s[2*j+1][1]);
            p[3] = pack2(s[2*j+1][2], s[2*j+1][3]);
            #pragma unroll
            for (int np = 0; np < 4; np++) {
                uint32_t vbh[4];
                uint32_t a = vb_ + (j * 16 + (lane & 15)) * ROWB
                           + (np * 16 + (lane >> 4) * 8) * 2;
                LDSM4T(vbh, a);
                MMA16816(o[2*np],   p, vbh);
                MMA16816(o[2*np+1], p, vbh + 2);
            }
        }
    }

    const int sp0 = q0 + wq0 + (lane >> 2);
    float g0 = gate[((size_t)b * SEQ + sp0) * NH + h] / l0;
    float g1 = gate[((size_t)b * SEQ + sp0 + 8) * NH + h] / l1;
    const size_t r0 = ((size_t)b * SEQ + sp0) * DIM + h * DKH;
    const size_t r1 = r0 + (size_t)8 * DIM;
    #pragma unroll
    for (int nt = 0; nt < 8; nt++) {
        const int col = nt * 8 + (lane & 3) * 2;
        *(uint32_t*)&ctx[r0 + col] = pack2(o[nt][0] * g0, o[nt][1] * g0);
        *(uint32_t*)&ctx[r1 + col] = pack2(o[nt][2] * g1, o[nt][3] * g1);
    }
}

// ---------------- mega prep kernel ----------------
__device__ void tsplit_body(const float* __restrict__ W, hf* __restrict__ T,
                            int K, int N, int bx, int by)
{
    __shared__ float t[32][33];
    int tx = threadIdx.x & 31, ty = threadIdx.x >> 5;
    int n0 = bx * 32, k0 = by * 32;
    #pragma unroll
    for (int i = 0; i < 4; i++)
        t[ty + i * 8][tx] = W[(size_t)(k0 + ty + i * 8) * N + n0 + tx];
    __syncthreads();
    #pragma unroll
    for (int i = 0; i < 4; i++)
        T[(size_t)(n0 + ty + i * 8) * K + k0 + tx] = __float2half_rn(t[tx][ty + i * 8]);
}

__global__ __launch_bounds__(256)
void prep_kernel(const float* __restrict__ x,
                 const float* __restrict__ wq, const float* __restrict__ wk,
                 const float* __restrict__ wv, const float* __restrict__ wo,
                 const float* __restrict__ w1, const float* __restrict__ w2,
                 const float* __restrict__ bq, const float* __restrict__ bk,
                 const float* __restrict__ bv, const float* __restrict__ wg,
                 hf* __restrict__ x16,
                 hf* __restrict__ wqkvT, hf* __restrict__ woT,
                 hf* __restrict__ w1T, hf* __restrict__ w2T,
                 float* __restrict__ bqkv, float* __restrict__ wgT)
{
    int id = blockIdx.x;
    if (id < 8192) {
        int i = id * 256 + threadIdx.x;
        float4 v = ((const float4*)x)[i];
        uint32_t pk[2] = {pack2(v.x, v.y), pack2(v.z, v.w)};
        ((uint2*)x16)[i] = *(uint2*)pk;
        return;
    }
    id -= 8192;
    if (id < 4096) {
        int w = id >> 10, r = id & 1023;
        const float* W = (w == 0) ? wq : (w == 1) ? wk : (w == 2) ? wv : wo;
        hf* T = (w < 3) ? wqkvT + (size_t)w * DIM * DIM : woT;
        tsplit_body(W, T, DIM, DIM, r & 31, r >> 5);
        return;
    }
    id -= 4096;
    if (id < 4096) {
        tsplit_body(w1, w1T, DIM, DFFN, id & 127, id >> 7);
        return;
    }
    id -= 4096;
    if (id < 4096) {
        tsplit_body(w2, w2T, DFFN, DIM, id & 31, id >> 5);
        return;
    }
    id -= 4096;
    if (id == 0) {
        for (int i = threadIdx.x; i < DIM; i += 256) {
            bqkv[i] = bq[i]; bqkv[DIM + i] = bk[i]; bqkv[2 * DIM + i] = bv[i];
        }
        for (int i = threadIdx.x; i < DIM * NH; i += 256)
            wgT[(i % NH) * DIM + i / NH] = wg[i];
    }
}

// ---------------- gate (coalesced wgT) ----------------
__global__ __launch_bounds__(256)
void gate_kernel(const float* __restrict__ x, const float* __restrict__ wgT,
                 const float* __restrict__ bg, float* __restrict__ gate)
{
    __shared__ float xs[8][DIM];
    int row0 = blockIdx.x * 8;
    for (int i = threadIdx.x; i < 8 * DIM; i += 256)
        ((float*)xs)[i] = x[(size_t)row0 * DIM + i];
    __syncthreads();
    int w = threadIdx.x >> 5, lane = threadIdx.x & 31;
    for (int t = w; t < 8 * NH; t += 8) {
        int r = t >> 4, h = t & 15;
        float s = 0.f;
        for (int d = lane; d < DIM; d += 32) s += xs[r][d] * wgT[h * DIM + d];
        #pragma unroll
        for (int o = 16; o; o >>= 1) s += __shfl_xor_sync(0xffffffffu, s, o);
        if (lane == 0)
            gate[(size_t)(row0 + r) * NH + h] = 1.f / (1.f + __expf(-(s + bg[h])));
    }
}

// ---------------- layernorm ----------------
__device__ __forceinline__ float blk_red(float v, float* sm, bool mx) {
    int lane = threadIdx.x & 31, w = threadIdx.x >> 5;
    #pragma unroll
    for (int o = 16; o; o >>= 1) {
        float t = __shfl_xor_sync(0xffffffffu, v, o);
        v = mx ? fmaxf(v, t) : v + t;
    }
    if (lane == 0) sm[w] = v;
    __syncthreads();
    if (w == 0) {
        float t = (lane < 8) ? sm[lane] : (mx ? -3.4e38f : 0.f);
        #pragma unroll
        for (int o = 4; o; o >>= 1) {
            float u = __shfl_xor_sync(0xffffffffu, t, o);
            t = mx ? fmaxf(t, u) : t + u;
        }
        if (lane == 0) sm[0] = t;
    }
    __syncthreads();
    float r = sm[0];
    __syncthreads();
    return r;
}

__global__ __launch_bounds__(256)
void ln_kernel(const float* __restrict__ in, const float* __restrict__ gamma,
               const float* __restrict__ beta, float* __restrict__ out,
               hf* __restrict__ o16)
{
    __shared__ float sm[32];
    int row = blockIdx.x;
    const float4 v = ((const float4*)(in + (size_t)row * DIM))[threadIdx.x];
    float s  = v.x + v.y + v.z + v.w;
    float s2 = v.x*v.x + v.y*v.y + v.z*v.z + v.w*v.w;
    s  = blk_red(s,  sm, false);
    s2 = blk_red(s2, sm, false);
    float mu  = s * (1.f / DIM);
    float var = s2 * (1.f / DIM) - mu * mu;
    float rs  = rsqrtf(var + 1e-5f);
    int n = threadIdx.x * 4;
    float4 gv = *(const float4*)(gamma + n);
    float4 bv = *(const float4*)(beta + n);
    float o[4] = {(v.x-mu)*rs*gv.x+bv.x, (v.y-mu)*rs*gv.y+bv.y,
                  (v.z-mu)*rs*gv.z+bv.z, (v.w-mu)*rs*gv.w+bv.w};
    ((float4*)(out + (size_t)row * DIM))[threadIdx.x] = make_float4(o[0],o[1],o[2],o[3]);
    if (o16) {
        uint32_t pk[2] = {pack2(o[0], o[1]), pack2(o[2], o[3])};
        *(uint2*)(o16 + (size_t)row * DIM + n) = *(uint2*)pk;
    }
}

// ---------------- launch ----------------
static const int SMGM = 3 * (128 * 144 + 128 * 144);   // 110592 (2 CTAs/SM)
static const int SMFL = 128 * 144 + 2 * (64 * 144) + 2 * (64 * 144) + 512; // 55808

extern "C" void kernel_launch(void* const* d_in, const int* in_sizes, int n_in,
                              void* d_out, int out_size)
{
    const float* x   = (const float*)d_in[0];
    const float* w_q = (const float*)d_in[1];  const float* b_q = (const float*)d_in[2];
    const float* w_k = (const float*)d_in[3];  const float* b_k = (const float*)d_in[4];
    const float* w_v = (const float*)d_in[5];  const float* b_v = (const float*)d_in[6];
    const float* w_o = (const float*)d_in[7];  const float* b_o = (const float*)d_in[8];
    const float* w_g = (const float*)d_in[9];  const float* b_g = (const float*)d_in[10];
    const float* w1  = (const float*)d_in[11]; const float* b1  = (const float*)d_in[12];
    const float* w2  = (const float*)d_in[13]; const float* b2  = (const float*)d_in[14];
    const float* g1  = (const float*)d_in[15]; const float* be1 = (const float*)d_in[16];
    const float* g2  = (const float*)d_in[17]; const float* be2 = (const float*)d_in[18];
    const int*  mask = (const int*)  d_in[19];
    float* out = (float*)d_out;

    #define SYM(p, s) void* p; cudaGetSymbolAddress(&p, s)
    SYM(x16, g_x16); SYM(qkv, g_qkv);
    SYM(gate, g_gate); SYM(wgT, g_wgT); SYM(ctx, g_ctx);
    SYM(y, g_y); SYM(x1, g_x1); SYM(x116, g_x116);
    SYM(h1, g_h1); SYM(y2, g_y2);
    SYM(wqkvT, g_wqkvT); SYM(woT, g_woT);
    SYM(w1T, g_w1T); SYM(w2T, g_w2T);
    SYM(bqkv, g_bqkv);
    #undef SYM

    cudaFuncSetAttribute(mma_gemm<9>,  cudaFuncAttributeMaxDynamicSharedMemorySize, SMGM);
    cudaFuncSetAttribute(mma_gemm<3>,  cudaFuncAttributeMaxDynamicSharedMemorySize, SMGM);
    cudaFuncSetAttribute(mma_gemm<13>, cudaFuncAttributeMaxDynamicSharedMemorySize, SMGM);
    cudaFuncSetAttribute(flash_kernel, cudaFuncAttributeMaxDynamicSharedMemorySize, SMFL);

    dim3 tb(256);
    // 1: prep
    prep_kernel<<<20481, tb>>>(x, w_q, w_k, w_v, w_o, w1, w2, b_q, b_k, b_v, w_g,
        (hf*)x16, (hf*)wqkvT, (hf*)woT, (hf*)w1T, (hf*)w2T,
        (float*)bqkv, (float*)wgT);

    // 2: merged QKV  [8192, 3072]
    mma_gemm<9><<<dim3(24, 64, 1), tb, SMGM>>>(
        (hf*)x16, DIM, (hf*)wqkvT, DIM,
        nullptr, (hf*)qkv, 3*DIM, (float*)bqkv, nullptr, 1.f, DIM);

    // 3: gate
    gate_kernel<<<MROWS / 8, tb>>>(x, (float*)wgT, b_g, (float*)gate);

    // 4: fused attention
    flash_kernel<<<dim3(SEQ/128, BATCH*NH), tb, SMFL>>>(
        (hf*)qkv, (float*)gate, mask, (hf*)ctx);

    // 5: y = x + ctx @ w_o + b_o
    mma_gemm<3><<<dim3(8, 64, 1), tb, SMGM>>>(
        (hf*)ctx, DIM, (hf*)woT, DIM,
        (float*)y, nullptr, DIM, b_o, x, 1.f, DIM);

    // 6: x1 = LN(y)
    ln_kernel<<<MROWS, tb>>>((float*)y, g1, be1, (float*)x1, (hf*)x116);

    // 7: h1 = gelu(x1 @ w1 + b1)
    mma_gemm<13><<<dim3(32, 64, 1), tb, SMGM>>>(
        (hf*)x116, DIM, (hf*)w1T, DIM,
        nullptr, (hf*)h1, DFFN, b1, nullptr, 1.f, DIM);

    // 8: y2 = x1 + h1 @ w2 + b2
    mma_gemm<3><<<dim3(8, 64, 1), tb, SMGM>>>(
        (hf*)h1, DFFN, (hf*)w2T, DFFN,
        (float*)y2, nullptr, DIM, b2, (const float*)x1, 1.f, DFFN);

    // 9: out = LN(y2)
    ln_kernel<<<MROWS, tb>>>((float*)y2, g2, be2, out, nullptr);
}